// round 1
// baseline (speedup 1.0000x reference)
#include <cuda_runtime.h>
#include <cuda_bf16.h>
#include <cstdint>

#define N_NODES 32768
#define N_PER   512
#define BGRAPH  64
#define E_EDGES 524288
#define NE      557056   // E + N_NODES self loops
#define C_IN    32
#define HDIM    128
#define KTLS    8
#define A_DIM   8

// ---------------- scratch (device globals; no allocs allowed) ----------------
__device__ float4 g_h[N_NODES * 32];     // h, 16 MB (float4 rows of 32)
__device__ float4 g_out[N_NODES * 32];   // aggregation target, 16 MB
__device__ float  g_as[N_NODES];
__device__ float  g_ad[N_NODES];
__device__ unsigned g_m[N_NODES];        // ordered-uint max
__device__ float  g_den[N_NODES];
__device__ float  g_e[NE];               // edge logits, then exp values
__device__ float  g_feats[BGRAPH * 1024];
__device__ float  g_v1[BGRAPH * 1024];
__device__ float  g_v2[BGRAPH * 256];
__device__ float  g_v3[BGRAPH * 64];
__device__ float  g_vo[BGRAPH * 1];
__device__ float  g_a1[BGRAPH * 1024];
__device__ float  g_a2[BGRAPH * 256];
__device__ float  g_a3[BGRAPH * 64];
__device__ float  g_ao[BGRAPH * A_DIM];

// ordered-uint encoding for float atomicMax (monotone for all finite floats)
__device__ __forceinline__ unsigned f2o(float f) {
    unsigned b = __float_as_uint(f);
    return (b & 0x80000000u) ? ~b : (b | 0x80000000u);
}
__device__ __forceinline__ float o2f(unsigned o) {
    unsigned b = (o & 0x80000000u) ? (o ^ 0x80000000u) : ~o;
    return __uint_as_float(b);
}

__device__ __forceinline__ void red_add_v4(float4* addr, float4 v) {
    asm volatile("red.global.add.v4.f32 [%0], {%1,%2,%3,%4};"
                 :: "l"(addr), "f"(v.x), "f"(v.y), "f"(v.z), "f"(v.w) : "memory");
}

// ---------------- kernels ----------------

// zero m/den/out. grid 4096 x 256 => exactly N_NODES*32 threads
__global__ void k_zero() {
    int i = blockIdx.x * blockDim.x + threadIdx.x;
    if (i < N_NODES) { g_m[i] = 0u; g_den[i] = 0.f; }
    g_out[i] = make_float4(0.f, 0.f, 0.f, 0.f);
}

// one block (128 thr) per node: h = x@W, as = h.att_src, ad = h.att_dst
__global__ void k_node(const float* __restrict__ x, const float* __restrict__ W,
                       const float* __restrict__ att_src, const float* __restrict__ att_dst) {
    int n = blockIdx.x;
    int t = threadIdx.x;
    __shared__ float xs[C_IN];
    if (t < C_IN) xs[t] = x[n * C_IN + t];
    __syncthreads();
    float acc = 0.f;
#pragma unroll
    for (int k = 0; k < C_IN; k++) acc = fmaf(xs[k], W[k * HDIM + t], acc);
    ((float*)g_h)[n * HDIM + t] = acc;
    float es = acc * att_src[t];
    float ed = acc * att_dst[t];
#pragma unroll
    for (int off = 16; off; off >>= 1) {
        es += __shfl_down_sync(0xFFFFFFFFu, es, off);
        ed += __shfl_down_sync(0xFFFFFFFFu, ed, off);
    }
    __shared__ float rs[4], rd[4];
    if ((t & 31) == 0) { rs[t >> 5] = es; rd[t >> 5] = ed; }
    __syncthreads();
    if (t == 0) {
        g_as[n] = rs[0] + rs[1] + rs[2] + rs[3];
        g_ad[n] = rd[0] + rd[1] + rd[2] + rd[3];
    }
}

// edge pass 1: logits + leaky relu + segment max (atomic on ordered uint)
__global__ void k_pass1(const int* __restrict__ ei) {
    int i = blockIdx.x * blockDim.x + threadIdx.x;
    if (i >= NE) return;
    int s, d;
    if (i < E_EDGES) { s = ei[i]; d = ei[E_EDGES + i]; }
    else             { s = d = i - E_EDGES; }
    float ev = g_as[s] + g_ad[d];
    ev = ev > 0.f ? ev : 0.2f * ev;
    g_e[i] = ev;
    atomicMax(&g_m[d], f2o(ev));
}

// edge pass 2: exp(e - m[dst]) + segment sum
__global__ void k_pass2(const int* __restrict__ ei) {
    int i = blockIdx.x * blockDim.x + threadIdx.x;
    if (i >= NE) return;
    int d = (i < E_EDGES) ? ei[E_EDGES + i] : (i - E_EDGES);
    float m = o2f(g_m[d]);
    float ex = __expf(g_e[i] - m);
    g_e[i] = ex;
    atomicAdd(&g_den[d], ex);
}

// edge pass 3: one warp per edge; out[dst] += h[src] * alpha (vector RED)
__global__ void k_pass3(const int* __restrict__ ei) {
    int gt = blockIdx.x * blockDim.x + threadIdx.x;
    int w = gt >> 5;
    int lane = gt & 31;
    if (w >= NE) return;
    int s, d;
    if (w < E_EDGES) { s = ei[w]; d = ei[E_EDGES + w]; }
    else             { s = d = w - E_EDGES; }
    float alpha = g_e[w] / (g_den[d] + 1e-16f);
    float4 hv = g_h[s * 32 + lane];
    float4 v = make_float4(hv.x * alpha, hv.y * alpha, hv.z * alpha, hv.w * alpha);
    red_add_v4(&g_out[d * 32 + lane], v);
}

// gather tls nodes, add bias, ELU (only 512 nodes need ELU)
__global__ void k_gather(const int* __restrict__ tls_idx, const float* __restrict__ b_gat) {
    int bk = blockIdx.x;          // 0..511 = b*K + k
    int t  = threadIdx.x;         // 0..127
    int b = bk >> 3, k = bk & 7;
    int g = b * N_PER + tls_idx[k];
    float v = ((const float*)g_out)[g * HDIM + t] + b_gat[t];
    v = v > 0.f ? v : expm1f(v);
    g_feats[b * 1024 + k * HDIM + t] = v;
}

// device-side buffer selection (host cannot take &__device__ symbol)
__device__ __forceinline__ float* buf(int id) {
    switch (id) {
        case 0: return g_feats;
        case 1: return g_v1; case 2: return g_v2; case 3: return g_v3; case 4: return g_vo;
        case 5: return g_a1; case 6: return g_a2; case 7: return g_a3; default: return g_ao;
    }
}

// C[64,N] = act(A[64,Kd] @ W[Kd,N] + b). 8 rows/thread, 128 cols/block.
// grid: (ceil(N/128), 8), block: 128
__global__ void k_mlp(int in_id, const float* __restrict__ W, const float* __restrict__ bias,
                      int out_id, int Kd, int Nn, int relu) {
    const float* A = buf(in_id);
    float* C = buf(out_id);
    int j  = blockIdx.x * 128 + threadIdx.x;
    int b0 = blockIdx.y * 8;
    float acc[8] = {0.f, 0.f, 0.f, 0.f, 0.f, 0.f, 0.f, 0.f};
    __shared__ float As[8][65];
    for (int kk = 0; kk < Kd; kk += 64) {
        __syncthreads();
        for (int u = threadIdx.x; u < 512; u += 128) {
            int r = u >> 6, c = u & 63;
            As[r][c] = A[(b0 + r) * Kd + kk + c];
        }
        __syncthreads();
#pragma unroll 4
        for (int k = 0; k < 64; k++) {
            float w = (j < Nn) ? W[(kk + k) * Nn + j] : 0.f;
#pragma unroll
            for (int r = 0; r < 8; r++) acc[r] = fmaf(As[r][k], w, acc[r]);
        }
    }
    if (j < Nn) {
        float bb = bias[j];
#pragma unroll
        for (int r = 0; r < 8; r++) {
            float v = acc[r] + bb;
            if (relu) v = fmaxf(v, 0.f);
            C[(b0 + r) * Nn + j] = v;
        }
    }
}

// dueling combine: out[b][j] = v[b] + a[b][j] - mean_j a[b][j]
__global__ void k_combine(float* __restrict__ out) {
    int tid = threadIdx.x;          // 512 threads
    int b = tid >> 3;
    float a = g_ao[tid];
    float s = a;
#pragma unroll
    for (int m = 1; m < 8; m <<= 1) s += __shfl_xor_sync(0xFFFFFFFFu, s, m);
    out[tid] = g_vo[b] + a - s * 0.125f;
}

// ---------------- launch ----------------
extern "C" void kernel_launch(void* const* d_in, const int* in_sizes, int n_in,
                              void* d_out, int out_size) {
    const float* x       = (const float*)d_in[0];
    const int*   ei      = (const int*)  d_in[1];
    const int*   tls     = (const int*)  d_in[2];
    const float* W       = (const float*)d_in[3];
    const float* att_src = (const float*)d_in[4];
    const float* att_dst = (const float*)d_in[5];
    const float* b_gat   = (const float*)d_in[6];
    const float* vW1 = (const float*)d_in[7];  const float* vb1 = (const float*)d_in[8];
    const float* vW2 = (const float*)d_in[9];  const float* vb2 = (const float*)d_in[10];
    const float* vW3 = (const float*)d_in[11]; const float* vb3 = (const float*)d_in[12];
    const float* vW4 = (const float*)d_in[13]; const float* vb4 = (const float*)d_in[14];
    const float* aW1 = (const float*)d_in[15]; const float* ab1 = (const float*)d_in[16];
    const float* aW2 = (const float*)d_in[17]; const float* ab2 = (const float*)d_in[18];
    const float* aW3 = (const float*)d_in[19]; const float* ab3 = (const float*)d_in[20];
    const float* aW4 = (const float*)d_in[21]; const float* ab4 = (const float*)d_in[22];

    k_zero<<<4096, 256>>>();
    k_node<<<N_NODES, 128>>>(x, W, att_src, att_dst);
    k_pass1<<<(NE + 255) / 256, 256>>>(ei);
    k_pass2<<<(NE + 255) / 256, 256>>>(ei);
    k_pass3<<<(NE * 32 + 255) / 256, 256>>>(ei);
    k_gather<<<BGRAPH * KTLS, 128>>>(tls, b_gat);

    k_mlp<<<dim3(8, 8), 128>>>(0, vW1, vb1, 1, 1024, 1024, 1);
    k_mlp<<<dim3(2, 8), 128>>>(1, vW2, vb2, 2, 1024, 256, 1);
    k_mlp<<<dim3(1, 8), 128>>>(2, vW3, vb3, 3, 256, 64, 1);
    k_mlp<<<dim3(1, 8), 128>>>(3, vW4, vb4, 4, 64, 1, 0);
    k_mlp<<<dim3(8, 8), 128>>>(0, aW1, ab1, 5, 1024, 1024, 1);
    k_mlp<<<dim3(2, 8), 128>>>(5, aW2, ab2, 6, 1024, 256, 1);
    k_mlp<<<dim3(1, 8), 128>>>(6, aW3, ab3, 7, 256, 64, 1);
    k_mlp<<<dim3(1, 8), 128>>>(7, aW4, ab4, 8, 64, A_DIM, 0);

    k_combine<<<1, 512>>>((float*)d_out);
}

// round 2
// speedup vs baseline: 2.9356x; 2.9356x over previous
#include <cuda_runtime.h>
#include <cuda_bf16.h>
#include <cstdint>
#include <math_constants.h>

#define N_NODES 32768
#define N_PER   512
#define BGRAPH  64
#define E_EDGES 524288
#define C_IN    32
#define HDIM    128
#define KTLS    8
#define A_DIM   8
#define NSLOTS  512          // BGRAPH * KTLS
#define ECAP    1024         // max edges per slot (avg ~17, Poisson tail safe)

// ---------------- scratch (device globals; no allocs allowed) ----------------
__device__ float g_as[N_NODES];
__device__ float g_ad[N_NODES];
__device__ int   g_cur[NSLOTS];
__device__ int   g_srcs[NSLOTS * ECAP];
__device__ float g_feats[BGRAPH * 1024];
__device__ float g_v1[BGRAPH * 1024];
__device__ float g_v2[BGRAPH * 256];
__device__ float g_v3[BGRAPH * 64];
__device__ float g_vo[BGRAPH * 1];
__device__ float g_a1[BGRAPH * 1024];
__device__ float g_a2[BGRAPH * 256];
__device__ float g_a3[BGRAPH * 64];
__device__ float g_ao[BGRAPH * A_DIM];

// ---------------- kernels ----------------

// grid 128 x 256 : per-node attention scalars as/ad = x . (W @ att_{src,dst})
// also zeroes the slot cursors.
__global__ void k_att(const float* __restrict__ x, const float* __restrict__ W,
                      const float* __restrict__ att_src, const float* __restrict__ att_dst) {
    __shared__ float ws[C_IN], wd[C_IN];
    int t = threadIdx.x;
    if (t < 64) {
        int c = t & 31;
        const float* av = (t < 32) ? att_src : att_dst;
        float s = 0.f;
#pragma unroll 8
        for (int d = 0; d < HDIM; d++) s = fmaf(W[c * HDIM + d], av[d], s);
        if (t < 32) ws[c] = s; else wd[c] = s;
    }
    __syncthreads();
    int n = blockIdx.x * 256 + t;               // exactly N_NODES threads
    const float4* xr = (const float4*)(x + n * C_IN);
    float s1 = 0.f, s2 = 0.f;
#pragma unroll
    for (int q = 0; q < 8; q++) {
        float4 v = xr[q];
        s1 = fmaf(v.x, ws[q*4+0], s1); s2 = fmaf(v.x, wd[q*4+0], s2);
        s1 = fmaf(v.y, ws[q*4+1], s1); s2 = fmaf(v.y, wd[q*4+1], s2);
        s1 = fmaf(v.z, ws[q*4+2], s1); s2 = fmaf(v.z, wd[q*4+2], s2);
        s1 = fmaf(v.w, ws[q*4+3], s1); s2 = fmaf(v.w, wd[q*4+3], s2);
    }
    g_as[n] = s1;
    g_ad[n] = s2;
    if (n < NSLOTS) g_cur[n] = 0;
}

// filter edges: dst is a target iff (dst & 511) in tls set. Append src to the
// matching (graph, k) slot buckets. Threads [E, E+NSLOTS) append self loops.
__global__ void k_edge(const int* __restrict__ ei, const int* __restrict__ tls) {
    __shared__ int tl[KTLS];
    if (threadIdx.x < KTLS) tl[threadIdx.x] = tls[threadIdx.x];
    __syncthreads();
    long i = (long)blockIdx.x * blockDim.x + threadIdx.x;
    if (i < E_EDGES) {
        int d = ei[E_EDGES + i];
        int loc = d & (N_PER - 1);
        int b = d >> 9;
        int s = -1;
#pragma unroll
        for (int k = 0; k < KTLS; k++) {
            if (tl[k] == loc) {
                if (s < 0) s = ei[i];
                int slot = b * KTLS + k;
                int p = atomicAdd(&g_cur[slot], 1);
                if (p < ECAP) g_srcs[slot * ECAP + p] = s;
            }
        }
    } else if (i < E_EDGES + NSLOTS) {
        int slot = (int)(i - E_EDGES);
        int b = slot >> 3, k = slot & 7;
        int n = b * N_PER + tl[k];
        int p = atomicAdd(&g_cur[slot], 1);
        if (p < ECAP) g_srcs[slot * ECAP + p] = n;
    }
}

// 512 blocks x 128 threads: per target node softmax + on-the-fly h + aggregation
// + bias + ELU, writing feats directly.
__global__ void k_agg(const float* __restrict__ x, const float* __restrict__ W,
                      const int* __restrict__ tls, const float* __restrict__ b_gat) {
    __shared__ float Ws[C_IN * HDIM];      // 16 KB
    __shared__ float e_s[ECAP];            // 4 KB
    __shared__ int   s_s[ECAP];            // 4 KB
    __shared__ float racc[4][HDIM];        // 2 KB
    __shared__ float rden[4];
    __shared__ float red4[4];
    __shared__ float m_sh;

    int slot = blockIdx.x;
    int b = slot >> 3, k = slot & 7;
    int t = threadIdx.x;
    int w = t >> 5, l = t & 31;
    int n = b * N_PER + tls[k];
    float ad_n = g_ad[n];
    int deg = g_cur[slot];
    if (deg > ECAP) deg = ECAP;

    // stage W into smem (float4)
    {
        const float4* Wg = (const float4*)W;
        float4* Wl = (float4*)Ws;
        for (int u = t; u < C_IN * HDIM / 4; u += 128) Wl[u] = Wg[u];
    }

    // pass 1: logits + cache + max
    float lmax = -CUDART_INF_F;
    for (int j = t; j < deg; j += 128) {
        int s = g_srcs[slot * ECAP + j];
        float e = g_as[s] + ad_n;
        e = e > 0.f ? e : 0.2f * e;
        e_s[j] = e;
        s_s[j] = s;
        lmax = fmaxf(lmax, e);
    }
#pragma unroll
    for (int off = 16; off; off >>= 1)
        lmax = fmaxf(lmax, __shfl_xor_sync(0xFFFFFFFFu, lmax, off));
    if (l == 0) red4[w] = lmax;
    __syncthreads();
    if (t == 0) m_sh = fmaxf(fmaxf(red4[0], red4[1]), fmaxf(red4[2], red4[3]));
    __syncthreads();
    float m = m_sh;

    // pass 2: per warp, one edge at a time; recompute h = x[src] @ W on the fly
    float4 acc = make_float4(0.f, 0.f, 0.f, 0.f);
    float den = 0.f;
    const float4* Ws4 = (const float4*)Ws;
    for (int j = w; j < deg; j += 4) {
        int s = s_s[j];
        float ex = __expf(e_s[j] - m);
        den += ex;
        float xv = x[s * C_IN + l];            // lane l holds x[s][l]
        float4 h = make_float4(0.f, 0.f, 0.f, 0.f);
#pragma unroll
        for (int c = 0; c < C_IN; c++) {
            float xc = __shfl_sync(0xFFFFFFFFu, xv, c);
            float4 wv = Ws4[c * 32 + l];       // W[c][4l..4l+3]
            h.x = fmaf(xc, wv.x, h.x);
            h.y = fmaf(xc, wv.y, h.y);
            h.z = fmaf(xc, wv.z, h.z);
            h.w = fmaf(xc, wv.w, h.w);
        }
        acc.x = fmaf(ex, h.x, acc.x);
        acc.y = fmaf(ex, h.y, acc.y);
        acc.z = fmaf(ex, h.z, acc.z);
        acc.w = fmaf(ex, h.w, acc.w);
    }
    *((float4*)&racc[w][4 * l]) = acc;
    if (l == 0) rden[w] = den;
    __syncthreads();

    float tot = racc[0][t] + racc[1][t] + racc[2][t] + racc[3][t];
    float dtot = rden[0] + rden[1] + rden[2] + rden[3];
    float v = tot / (dtot + 1e-16f) + b_gat[t];
    v = v > 0.f ? v : expm1f(v);
    g_feats[b * (KTLS * HDIM) + k * HDIM + t] = v;
}

// device-side buffer selection
__device__ __forceinline__ float* buf(int id) {
    switch (id) {
        case 0: return g_feats;
        case 1: return g_v1; case 2: return g_v2; case 3: return g_v3; case 4: return g_vo;
        case 5: return g_a1; case 6: return g_a2; case 7: return g_a3; default: return g_ao;
    }
}

// fused v/a linear layer. grid (gx, 16, 2), block 128. 4 rows per block.
__global__ void k_mlp2(int inv, int ina,
                       const float* __restrict__ Wv, const float* __restrict__ bv,
                       const float* __restrict__ Wa, const float* __restrict__ ba,
                       int outv, int outa, int Kd, int Nv, int Na, int relu) {
    int z = blockIdx.z;
    const float* A = buf(z ? ina : inv);
    const float* Wm = z ? Wa : Wv;
    const float* bs = z ? ba : bv;
    float* C = buf(z ? outa : outv);
    int Nn = z ? Na : Nv;

    int j  = blockIdx.x * 128 + threadIdx.x;
    int b0 = blockIdx.y * 4;
    float acc[4] = {0.f, 0.f, 0.f, 0.f};
    __shared__ float As[4][65];
    for (int kk = 0; kk < Kd; kk += 64) {
        __syncthreads();
        for (int u = threadIdx.x; u < 256; u += 128) {
            int r = u >> 6, c = u & 63;
            As[r][c] = A[(b0 + r) * Kd + kk + c];
        }
        __syncthreads();
#pragma unroll 8
        for (int kq = 0; kq < 64; kq++) {
            float wv = (j < Nn) ? Wm[(kk + kq) * Nn + j] : 0.f;
#pragma unroll
            for (int r = 0; r < 4; r++) acc[r] = fmaf(As[r][kq], wv, acc[r]);
        }
    }
    if (j < Nn) {
        float bb = bs[j];
#pragma unroll
        for (int r = 0; r < 4; r++) {
            float v = acc[r] + bb;
            if (relu) v = fmaxf(v, 0.f);
            C[(b0 + r) * Nn + j] = v;
        }
    }
}

// dueling combine
__global__ void k_combine(float* __restrict__ out) {
    int tid = threadIdx.x;          // 512 threads
    int b = tid >> 3;
    float a = g_ao[tid];
    float s = a;
#pragma unroll
    for (int m = 1; m < 8; m <<= 1) s += __shfl_xor_sync(0xFFFFFFFFu, s, m);
    out[tid] = g_vo[b] + a - s * 0.125f;
}

// ---------------- launch ----------------
extern "C" void kernel_launch(void* const* d_in, const int* in_sizes, int n_in,
                              void* d_out, int out_size) {
    const float* x       = (const float*)d_in[0];
    const int*   ei      = (const int*)  d_in[1];
    const int*   tls     = (const int*)  d_in[2];
    const float* W       = (const float*)d_in[3];
    const float* att_src = (const float*)d_in[4];
    const float* att_dst = (const float*)d_in[5];
    const float* b_gat   = (const float*)d_in[6];
    const float* vW1 = (const float*)d_in[7];  const float* vb1 = (const float*)d_in[8];
    const float* vW2 = (const float*)d_in[9];  const float* vb2 = (const float*)d_in[10];
    const float* vW3 = (const float*)d_in[11]; const float* vb3 = (const float*)d_in[12];
    const float* vW4 = (const float*)d_in[13]; const float* vb4 = (const float*)d_in[14];
    const float* aW1 = (const float*)d_in[15]; const float* ab1 = (const float*)d_in[16];
    const float* aW2 = (const float*)d_in[17]; const float* ab2 = (const float*)d_in[18];
    const float* aW3 = (const float*)d_in[19]; const float* ab3 = (const float*)d_in[20];
    const float* aW4 = (const float*)d_in[21]; const float* ab4 = (const float*)d_in[22];

    k_att<<<128, 256>>>(x, W, att_src, att_dst);
    k_edge<<<(E_EDGES + NSLOTS + 255) / 256, 256>>>(ei, tls);
    k_agg<<<NSLOTS, 128>>>(x, W, tls, b_gat);

    k_mlp2<<<dim3(8, 16, 2), 128>>>(0, 0, vW1, vb1, aW1, ab1, 1, 5, 1024, 1024, 1024, 1);
    k_mlp2<<<dim3(2, 16, 2), 128>>>(1, 5, vW2, vb2, aW2, ab2, 2, 6, 1024, 256, 256, 1);
    k_mlp2<<<dim3(1, 16, 2), 128>>>(2, 6, vW3, vb3, aW3, ab3, 3, 7, 256, 64, 64, 1);
    k_mlp2<<<dim3(1, 16, 2), 128>>>(3, 7, vW4, vb4, aW4, ab4, 4, 8, 64, 1, A_DIM, 0);

    k_combine<<<1, 512>>>((float*)d_out);
}

// round 3
// speedup vs baseline: 6.6148x; 2.2533x over previous
#include <cuda_runtime.h>
#include <cuda_bf16.h>
#include <cstdint>
#include <math_constants.h>

#define N_NODES 32768
#define N_PER   512
#define BGRAPH  64
#define E_EDGES 524288
#define C_IN    32
#define HDIM    128
#define KTLS    8
#define A_DIM   8
#define NSLOTS  512
#define ECAP    1024
#define KCH     64        // GEMM split-K chunk

// ---------------- scratch (device globals; no allocs allowed) ----------------
__device__ float g_as[N_NODES];
__device__ float g_ad[N_NODES];
__device__ int   g_cur[NSLOTS];
__device__ int   g_srcs[NSLOTS * ECAP];
__device__ __align__(16) float g_feats[BGRAPH * 1024];
__device__ __align__(16) float g_h1[BGRAPH * 2048];
__device__ __align__(16) float g_h2[BGRAPH * 512];
__device__ __align__(16) float g_h3[BGRAPH * 128];
__device__ __align__(16) float g_p1[16 * BGRAPH * 2048];   // 8 MB partials L1
__device__ __align__(16) float g_p2[16 * BGRAPH * 512];
__device__ __align__(16) float g_p3[4  * BGRAPH * 128];

// ---------------- graph-side kernels (unchanged, proven) ----------------

__global__ void k_att(const float* __restrict__ x, const float* __restrict__ W,
                      const float* __restrict__ att_src, const float* __restrict__ att_dst) {
    __shared__ float ws[C_IN], wd[C_IN];
    int t = threadIdx.x;
    if (t < 64) {
        int c = t & 31;
        const float* av = (t < 32) ? att_src : att_dst;
        float s = 0.f;
#pragma unroll 8
        for (int d = 0; d < HDIM; d++) s = fmaf(W[c * HDIM + d], av[d], s);
        if (t < 32) ws[c] = s; else wd[c] = s;
    }
    __syncthreads();
    int n = blockIdx.x * 256 + t;
    const float4* xr = (const float4*)(x + n * C_IN);
    float s1 = 0.f, s2 = 0.f;
#pragma unroll
    for (int q = 0; q < 8; q++) {
        float4 v = xr[q];
        s1 = fmaf(v.x, ws[q*4+0], s1); s2 = fmaf(v.x, wd[q*4+0], s2);
        s1 = fmaf(v.y, ws[q*4+1], s1); s2 = fmaf(v.y, wd[q*4+1], s2);
        s1 = fmaf(v.z, ws[q*4+2], s1); s2 = fmaf(v.z, wd[q*4+2], s2);
        s1 = fmaf(v.w, ws[q*4+3], s1); s2 = fmaf(v.w, wd[q*4+3], s2);
    }
    g_as[n] = s1;
    g_ad[n] = s2;
    if (n < NSLOTS) g_cur[n] = 0;
}

__global__ void k_edge(const int* __restrict__ ei, const int* __restrict__ tls) {
    __shared__ int tl[KTLS];
    if (threadIdx.x < KTLS) tl[threadIdx.x] = tls[threadIdx.x];
    __syncthreads();
    long i = (long)blockIdx.x * blockDim.x + threadIdx.x;
    if (i < E_EDGES) {
        int d = ei[E_EDGES + i];
        int loc = d & (N_PER - 1);
        int b = d >> 9;
        int s = -1;
#pragma unroll
        for (int k = 0; k < KTLS; k++) {
            if (tl[k] == loc) {
                if (s < 0) s = ei[i];
                int slot = b * KTLS + k;
                int p = atomicAdd(&g_cur[slot], 1);
                if (p < ECAP) g_srcs[slot * ECAP + p] = s;
            }
        }
    } else if (i < E_EDGES + NSLOTS) {
        int slot = (int)(i - E_EDGES);
        int b = slot >> 3, k = slot & 7;
        int n = b * N_PER + tl[k];
        int p = atomicAdd(&g_cur[slot], 1);
        if (p < ECAP) g_srcs[slot * ECAP + p] = n;
    }
}

__global__ void k_agg(const float* __restrict__ x, const float* __restrict__ W,
                      const int* __restrict__ tls, const float* __restrict__ b_gat) {
    __shared__ float Ws[C_IN * HDIM];
    __shared__ float e_s[ECAP];
    __shared__ int   s_s[ECAP];
    __shared__ float racc[4][HDIM];
    __shared__ float rden[4];
    __shared__ float red4[4];
    __shared__ float m_sh;

    int slot = blockIdx.x;
    int b = slot >> 3, k = slot & 7;
    int t = threadIdx.x;
    int w = t >> 5, l = t & 31;
    int n = b * N_PER + tls[k];
    float ad_n = g_ad[n];
    int deg = g_cur[slot];
    if (deg > ECAP) deg = ECAP;

    {
        const float4* Wg = (const float4*)W;
        float4* Wl = (float4*)Ws;
        for (int u = t; u < C_IN * HDIM / 4; u += 128) Wl[u] = Wg[u];
    }

    float lmax = -CUDART_INF_F;
    for (int j = t; j < deg; j += 128) {
        int s = g_srcs[slot * ECAP + j];
        float e = g_as[s] + ad_n;
        e = e > 0.f ? e : 0.2f * e;
        e_s[j] = e;
        s_s[j] = s;
        lmax = fmaxf(lmax, e);
    }
#pragma unroll
    for (int off = 16; off; off >>= 1)
        lmax = fmaxf(lmax, __shfl_xor_sync(0xFFFFFFFFu, lmax, off));
    if (l == 0) red4[w] = lmax;
    __syncthreads();
    if (t == 0) m_sh = fmaxf(fmaxf(red4[0], red4[1]), fmaxf(red4[2], red4[3]));
    __syncthreads();
    float m = m_sh;

    float4 acc = make_float4(0.f, 0.f, 0.f, 0.f);
    float den = 0.f;
    const float4* Ws4 = (const float4*)Ws;
    for (int j = w; j < deg; j += 4) {
        int s = s_s[j];
        float ex = __expf(e_s[j] - m);
        den += ex;
        float xv = x[s * C_IN + l];
        float4 h = make_float4(0.f, 0.f, 0.f, 0.f);
#pragma unroll
        for (int c = 0; c < C_IN; c++) {
            float xc = __shfl_sync(0xFFFFFFFFu, xv, c);
            float4 wv = Ws4[c * 32 + l];
            h.x = fmaf(xc, wv.x, h.x);
            h.y = fmaf(xc, wv.y, h.y);
            h.z = fmaf(xc, wv.z, h.z);
            h.w = fmaf(xc, wv.w, h.w);
        }
        acc.x = fmaf(ex, h.x, acc.x);
        acc.y = fmaf(ex, h.y, acc.y);
        acc.z = fmaf(ex, h.z, acc.z);
        acc.w = fmaf(ex, h.w, acc.w);
    }
    *((float4*)&racc[w][4 * l]) = acc;
    if (l == 0) rden[w] = den;
    __syncthreads();

    float tot = racc[0][t] + racc[1][t] + racc[2][t] + racc[3][t];
    float dtot = rden[0] + rden[1] + rden[2] + rden[3];
    float v = tot / (dtot + 1e-16f) + b_gat[t];
    v = v > 0.f ? v : expm1f(v);
    g_feats[b * (KTLS * HDIM) + k * HDIM + t] = v;
}

// ---------------- MLP: real split-K SGEMM ----------------
// Block: 64 rows x 128 cols, K-chunk = 64. 128 threads, thread tile 8x8.
// grid (Ntiles, Kd/KCH, 2). Partials P[(chunk*64 + row)*Ntot + z*Nhead + col].
#define AS_STRIDE 68
#define WS_STRIDE 132
#define GEMM_SMEM ((KCH * AS_STRIDE + KCH * WS_STRIDE) * 4)

__global__ void __launch_bounds__(128) k_gemm(
        const float* __restrict__ Av, const float* __restrict__ Aa, int lda,
        const float* __restrict__ Wv, const float* __restrict__ Wa,
        float* __restrict__ P, int Kd, int Nhead, int Ntot) {
    extern __shared__ float sm[];
    float* As = sm;                      // [KCH][AS_STRIDE] transposed: As[k][row]
    float* Ws = sm + KCH * AS_STRIDE;    // [KCH][WS_STRIDE]

    int z  = blockIdx.z;
    const float* A  = z ? Aa : Av;
    const float* Wg = z ? Wa : Wv;
    int k0 = blockIdx.y * KCH;
    int j0 = blockIdx.x * 128;
    int tid = threadIdx.x;

    // load A chunk (64 rows x KCH k), transpose into As[k][row]
    for (int e = tid; e < 64 * (KCH / 4); e += 128) {
        int r = e >> 4, kq = e & 15;            // kq: float4 index along k
        float4 v = *(const float4*)(A + r * lda + k0 + kq * 4);
        As[(kq * 4 + 0) * AS_STRIDE + r] = v.x;
        As[(kq * 4 + 1) * AS_STRIDE + r] = v.y;
        As[(kq * 4 + 2) * AS_STRIDE + r] = v.z;
        As[(kq * 4 + 3) * AS_STRIDE + r] = v.w;
    }
    // load W chunk (KCH x 128 cols)
    for (int e = tid; e < KCH * 32; e += 128) {
        int kk = e >> 5, jq = e & 31;
        int j = j0 + jq * 4;
        if (j < Nhead) {
            float4 v = *(const float4*)(Wg + (long)(k0 + kk) * Nhead + j);
            *(float4*)&Ws[kk * WS_STRIDE + jq * 4] = v;
        }
    }
    __syncthreads();

    int trow = tid >> 4;          // 0..7 -> rows trow*8..+7
    int tcol = tid & 15;          // 0..15 -> cols tcol*8..+7
    int r0 = trow * 8, jb = tcol * 8;

    float acc[8][8];
#pragma unroll
    for (int i = 0; i < 8; i++)
#pragma unroll
        for (int j = 0; j < 8; j++) acc[i][j] = 0.f;

#pragma unroll 4
    for (int kk = 0; kk < KCH; kk++) {
        float4 a0 = *(float4*)&As[kk * AS_STRIDE + r0];
        float4 a1 = *(float4*)&As[kk * AS_STRIDE + r0 + 4];
        float4 w0 = *(float4*)&Ws[kk * WS_STRIDE + jb];
        float4 w1 = *(float4*)&Ws[kk * WS_STRIDE + jb + 4];
        float av[8] = {a0.x, a0.y, a0.z, a0.w, a1.x, a1.y, a1.z, a1.w};
        float wv[8] = {w0.x, w0.y, w0.z, w0.w, w1.x, w1.y, w1.z, w1.w};
#pragma unroll
        for (int i = 0; i < 8; i++)
#pragma unroll
            for (int j = 0; j < 8; j++) acc[i][j] = fmaf(av[i], wv[j], acc[i][j]);
    }

    long base = (long)(blockIdx.y * 64) * Ntot + z * Nhead + j0 + jb;
#pragma unroll
    for (int i = 0; i < 8; i++) {
        int row = r0 + i;
        if (j0 + jb < Nhead) {
            *(float4*)(P + base + (long)row * Ntot)     = make_float4(acc[i][0], acc[i][1], acc[i][2], acc[i][3]);
            *(float4*)(P + base + (long)row * Ntot + 4) = make_float4(acc[i][4], acc[i][5], acc[i][6], acc[i][7]);
        }
    }
}

// sum split-K partials + bias + relu
__global__ void k_ep(const float* __restrict__ P, float* __restrict__ O,
                     const float* __restrict__ bv, const float* __restrict__ ba,
                     int Nhead, int Ntot, int nch) {
    int i = blockIdx.x * 256 + threadIdx.x;   // over 64*Ntot
    int col = i % Ntot;
    float s = 0.f;
    for (int c = 0; c < nch; c++) s += P[(long)c * 64 * Ntot + i];
    s += (col < Nhead) ? bv[col] : ba[col - Nhead];
    O[i] = fmaxf(s, 0.f);
}

// layer 4 + dueling combine: 1 block, 576 threads
__global__ void k_final(const float* __restrict__ vW4, const float* __restrict__ vb4,
                        const float* __restrict__ aW4, const float* __restrict__ ab4,
                        float* __restrict__ out) {
    __shared__ float res[BGRAPH][9];
    int tid = threadIdx.x;
    if (tid < 576) {
        int b = tid / 9, j = tid % 9;
        const float* hrow = g_h3 + b * 128 + (j == 0 ? 0 : 64);
        float s = (j == 0) ? vb4[0] : ab4[j - 1];
        if (j == 0) {
#pragma unroll 8
            for (int c = 0; c < 64; c++) s = fmaf(hrow[c], vW4[c], s);
        } else {
#pragma unroll 8
            for (int c = 0; c < 64; c++) s = fmaf(hrow[c], aW4[c * A_DIM + (j - 1)], s);
        }
        res[b][j] = s;
    }
    __syncthreads();
    if (tid < 512) {
        int b = tid >> 3, i = tid & 7;
        float m = 0.f;
#pragma unroll
        for (int q = 1; q < 9; q++) m += res[b][q];
        m *= 0.125f;
        out[tid] = res[b][0] + res[b][1 + i] - m;
    }
}

// ---------------- launch ----------------
extern "C" void kernel_launch(void* const* d_in, const int* in_sizes, int n_in,
                              void* d_out, int out_size) {
    const float* x       = (const float*)d_in[0];
    const int*   ei      = (const int*)  d_in[1];
    const int*   tls     = (const int*)  d_in[2];
    const float* W       = (const float*)d_in[3];
    const float* att_src = (const float*)d_in[4];
    const float* att_dst = (const float*)d_in[5];
    const float* b_gat   = (const float*)d_in[6];
    const float* vW1 = (const float*)d_in[7];  const float* vb1 = (const float*)d_in[8];
    const float* vW2 = (const float*)d_in[9];  const float* vb2 = (const float*)d_in[10];
    const float* vW3 = (const float*)d_in[11]; const float* vb3 = (const float*)d_in[12];
    const float* vW4 = (const float*)d_in[13]; const float* vb4 = (const float*)d_in[14];
    const float* aW1 = (const float*)d_in[15]; const float* ab1 = (const float*)d_in[16];
    const float* aW2 = (const float*)d_in[17]; const float* ab2 = (const float*)d_in[18];
    const float* aW3 = (const float*)d_in[19]; const float* ab3 = (const float*)d_in[20];
    const float* aW4 = (const float*)d_in[21]; const float* ab4 = (const float*)d_in[22];

    static int smem_set = 0;
    if (!smem_set) {
        cudaFuncSetAttribute(k_gemm, cudaFuncAttributeMaxDynamicSharedMemorySize, GEMM_SMEM);
        smem_set = 1;
    }

    float* p1 = nullptr; float* p2 = nullptr; float* p3 = nullptr;
    float* h1 = nullptr; float* h2 = nullptr; float* h3 = nullptr; float* ft = nullptr;
    cudaGetSymbolAddress((void**)&p1, g_p1);
    cudaGetSymbolAddress((void**)&p2, g_p2);
    cudaGetSymbolAddress((void**)&p3, g_p3);
    cudaGetSymbolAddress((void**)&h1, g_h1);
    cudaGetSymbolAddress((void**)&h2, g_h2);
    cudaGetSymbolAddress((void**)&h3, g_h3);
    cudaGetSymbolAddress((void**)&ft, g_feats);

    k_att<<<128, 256>>>(x, W, att_src, att_dst);
    k_edge<<<(E_EDGES + NSLOTS + 255) / 256, 256>>>(ei, tls);
    k_agg<<<NSLOTS, 128>>>(x, W, tls, b_gat);

    // L1: K=1024, Nhead=1024, Ntot=2048; grid (8,16,2)
    k_gemm<<<dim3(8, 16, 2), 128, GEMM_SMEM>>>(ft, ft, 1024, vW1, aW1, p1, 1024, 1024, 2048);
    k_ep<<<(64 * 2048) / 256, 256>>>(p1, h1, vb1, ab1, 1024, 2048, 16);

    // L2: K=1024, Nhead=256, Ntot=512; grid (2,16,2)
    k_gemm<<<dim3(2, 16, 2), 128, GEMM_SMEM>>>(h1, h1 + 1024, 2048, vW2, aW2, p2, 1024, 256, 512);
    k_ep<<<(64 * 512) / 256, 256>>>(p2, h2, vb2, ab2, 256, 512, 16);

    // L3: K=256, Nhead=64, Ntot=128; grid (1,4,2)
    k_gemm<<<dim3(1, 4, 2), 128, GEMM_SMEM>>>(h2, h2 + 256, 512, vW3, aW3, p3, 256, 64, 128);
    k_ep<<<(64 * 128) / 256, 256>>>(p3, h3, vb3, ab3, 64, 128, 4);

    k_final<<<1, 576>>>(vW4, vb4, aW4, ab4, (float*)d_out);
}

// round 4
// speedup vs baseline: 6.8239x; 1.0316x over previous
#include <cuda_runtime.h>
#include <cstdint>
#include <math_constants.h>

#define N_NODES 32768
#define N_PER   512
#define BGRAPH  64
#define E_EDGES 524288
#define C_IN    32
#define HDIM    128
#define KTLS    8
#define A_DIM   8
#define NSLOTS  512
#define ECAP    1024
#define KCH     32

// ---------------- scratch (device globals; no allocs allowed) ----------------
__device__ float g_as[N_NODES];
__device__ float g_ad[N_NODES];
__device__ int   g_cur[NSLOTS];          // zero at load; k_agg re-zeros each run
__device__ int   g_srcs[NSLOTS * ECAP];
__device__ __align__(16) float g_feats[BGRAPH * 1024];
__device__ __align__(16) float g_p1[32 * BGRAPH * 2048];   // 16 MB partials L1
__device__ __align__(16) float g_p2[32 * BGRAPH * 512];    // 4 MB
__device__ __align__(16) float g_p3[8  * BGRAPH * 128];

// ---------------- fused att + edge-filter kernel ----------------
// blocks [0,128): per-node attention scalars; blocks [128,128+2050): edge filter.
__global__ void k_pre(const float* __restrict__ x, const float* __restrict__ W,
                      const float* __restrict__ att_src, const float* __restrict__ att_dst,
                      const int* __restrict__ ei, const int* __restrict__ tls) {
    __shared__ float ws[C_IN], wd[C_IN];
    __shared__ int tl[KTLS];
    int t = threadIdx.x;
    if (blockIdx.x < 128) {
        if (t < 64) {
            int c = t & 31;
            const float* av = (t < 32) ? att_src : att_dst;
            float s = 0.f;
#pragma unroll 8
            for (int d = 0; d < HDIM; d++) s = fmaf(W[c * HDIM + d], av[d], s);
            if (t < 32) ws[c] = s; else wd[c] = s;
        }
        __syncthreads();
        int n = blockIdx.x * 256 + t;
        const float4* xr = (const float4*)(x + n * C_IN);
        float s1 = 0.f, s2 = 0.f;
#pragma unroll
        for (int q = 0; q < 8; q++) {
            float4 v = xr[q];
            s1 = fmaf(v.x, ws[q*4+0], s1); s2 = fmaf(v.x, wd[q*4+0], s2);
            s1 = fmaf(v.y, ws[q*4+1], s1); s2 = fmaf(v.y, wd[q*4+1], s2);
            s1 = fmaf(v.z, ws[q*4+2], s1); s2 = fmaf(v.z, wd[q*4+2], s2);
            s1 = fmaf(v.w, ws[q*4+3], s1); s2 = fmaf(v.w, wd[q*4+3], s2);
        }
        g_as[n] = s1;
        g_ad[n] = s2;
    } else {
        if (t < KTLS) tl[t] = tls[t];
        __syncthreads();
        long i = (long)(blockIdx.x - 128) * 256 + t;     // < 524800 exactly
        if (i < E_EDGES) {
            int d = ei[E_EDGES + i];
            int loc = d & (N_PER - 1);
            int b = d >> 9;
            int s = -1;
#pragma unroll
            for (int k = 0; k < KTLS; k++) {
                if (tl[k] == loc) {
                    if (s < 0) s = ei[i];
                    int slot = b * KTLS + k;
                    int p = atomicAdd(&g_cur[slot], 1);
                    if (p < ECAP) g_srcs[slot * ECAP + p] = s;
                }
            }
        } else {                                          // self loops
            int slot = (int)(i - E_EDGES);
            int b = slot >> 3, k = slot & 7;
            int n = b * N_PER + tl[k];
            int p = atomicAdd(&g_cur[slot], 1);
            if (p < ECAP) g_srcs[slot * ECAP + p] = n;
        }
    }
}

// ---------------- per-target softmax + aggregation -> feats ----------------
__global__ void k_agg(const float* __restrict__ x, const float* __restrict__ W,
                      const int* __restrict__ tls, const float* __restrict__ b_gat) {
    __shared__ float Ws[C_IN * HDIM];
    __shared__ float e_s[ECAP];
    __shared__ int   s_s[ECAP];
    __shared__ float racc[4][HDIM];
    __shared__ float rden[4];
    __shared__ float red4[4];
    __shared__ float m_sh;

    int slot = blockIdx.x;
    int b = slot >> 3, k = slot & 7;
    int t = threadIdx.x;
    int w = t >> 5, l = t & 31;
    int n = b * N_PER + tls[k];
    float ad_n = g_ad[n];
    int deg = g_cur[slot];
    if (deg > ECAP) deg = ECAP;

    {
        const float4* Wg = (const float4*)W;
        float4* Wl = (float4*)Ws;
        for (int u = t; u < C_IN * HDIM / 4; u += 128) Wl[u] = Wg[u];
    }

    float lmax = -CUDART_INF_F;
    for (int j = t; j < deg; j += 128) {
        int s = g_srcs[slot * ECAP + j];
        float e = g_as[s] + ad_n;
        e = e > 0.f ? e : 0.2f * e;
        e_s[j] = e;
        s_s[j] = s;
        lmax = fmaxf(lmax, e);
    }
#pragma unroll
    for (int off = 16; off; off >>= 1)
        lmax = fmaxf(lmax, __shfl_xor_sync(0xFFFFFFFFu, lmax, off));
    if (l == 0) red4[w] = lmax;
    __syncthreads();
    if (t == 0) m_sh = fmaxf(fmaxf(red4[0], red4[1]), fmaxf(red4[2], red4[3]));
    __syncthreads();
    float m = m_sh;

    float4 acc = make_float4(0.f, 0.f, 0.f, 0.f);
    float den = 0.f;
    const float4* Ws4 = (const float4*)Ws;
    for (int j = w; j < deg; j += 4) {
        int s = s_s[j];
        float ex = __expf(e_s[j] - m);
        den += ex;
        float xv = x[s * C_IN + l];
        float4 h = make_float4(0.f, 0.f, 0.f, 0.f);
#pragma unroll
        for (int c = 0; c < C_IN; c++) {
            float xc = __shfl_sync(0xFFFFFFFFu, xv, c);
            float4 wv = Ws4[c * 32 + l];
            h.x = fmaf(xc, wv.x, h.x);
            h.y = fmaf(xc, wv.y, h.y);
            h.z = fmaf(xc, wv.z, h.z);
            h.w = fmaf(xc, wv.w, h.w);
        }
        acc.x = fmaf(ex, h.x, acc.x);
        acc.y = fmaf(ex, h.y, acc.y);
        acc.z = fmaf(ex, h.z, acc.z);
        acc.w = fmaf(ex, h.w, acc.w);
    }
    *((float4*)&racc[w][4 * l]) = acc;
    if (l == 0) rden[w] = den;
    __syncthreads();

    float tot = racc[0][t] + racc[1][t] + racc[2][t] + racc[3][t];
    float dtot = rden[0] + rden[1] + rden[2] + rden[3];
    float v = tot / (dtot + 1e-16f) + b_gat[t];
    v = v > 0.f ? v : expm1f(v);
    g_feats[b * (KTLS * HDIM) + k * HDIM + t] = v;
    if (t == 0) g_cur[slot] = 0;       // reset cursor for next graph replay
}

// ---------------- split-K SGEMM with fused input epilogue ----------------
// Block tile: 64 rows x 128 cols x KCH=32. 128 threads, 8x8 thread tile,
// packed fma.rn.f32x2 inner loop. If nch_in > 0, the A tile is produced by
// summing the previous layer's split-K partials + bias + ReLU while staging.
#define AS_STRIDE 68
#define WS_STRIDE 132

union F4U { float4 v; unsigned long long u[2]; float f[4]; };

__global__ void __launch_bounds__(128) k_gemm(
        const float* __restrict__ Ain, int nch_in, int ldin, int zstride,
        const float* __restrict__ bv_in, const float* __restrict__ ba_in,
        const float* __restrict__ Wv, const float* __restrict__ Wa,
        float* __restrict__ P, int Nhead, int Ntot) {
    __shared__ float As[KCH * AS_STRIDE];
    __shared__ float Ws[KCH * WS_STRIDE];

    int z  = blockIdx.z;
    const float* Wg = z ? Wa : Wv;
    int k0 = blockIdx.y * KCH;
    int j0 = blockIdx.x * 128;
    int tid = threadIdx.x;

    // stage A chunk (64 rows x KCH), transposed As[k][row]; optionally fuse
    // previous layer epilogue (sum partial chunks + bias + relu)
    {
        int colbase = z * zstride + k0;
        const float* bin = z ? ba_in : bv_in;
        for (int e = tid; e < 64 * (KCH / 4); e += 128) {
            int r = e >> 3, kq = e & 7;
            const float* src = Ain + (long)r * ldin + colbase + kq * 4;
            float4 v;
            if (nch_in == 0) {
                v = *(const float4*)src;
            } else {
                float4 sacc = make_float4(0.f, 0.f, 0.f, 0.f);
                for (int c = 0; c < nch_in; c++) {
                    float4 p = *(const float4*)(src + (long)c * 64 * ldin);
                    sacc.x += p.x; sacc.y += p.y; sacc.z += p.z; sacc.w += p.w;
                }
                float4 bb = *(const float4*)(bin + k0 + kq * 4);
                v.x = fmaxf(sacc.x + bb.x, 0.f);
                v.y = fmaxf(sacc.y + bb.y, 0.f);
                v.z = fmaxf(sacc.z + bb.z, 0.f);
                v.w = fmaxf(sacc.w + bb.w, 0.f);
            }
            As[(kq * 4 + 0) * AS_STRIDE + r] = v.x;
            As[(kq * 4 + 1) * AS_STRIDE + r] = v.y;
            As[(kq * 4 + 2) * AS_STRIDE + r] = v.z;
            As[(kq * 4 + 3) * AS_STRIDE + r] = v.w;
        }
    }
    // stage W chunk (KCH x 128 cols)
    for (int e = tid; e < KCH * 32; e += 128) {
        int kk = e >> 5, jq = e & 31;
        int j = j0 + jq * 4;
        if (j < Nhead) {
            float4 v = *(const float4*)(Wg + (long)(k0 + kk) * Nhead + j);
            *(float4*)&Ws[kk * WS_STRIDE + jq * 4] = v;
        }
    }
    __syncthreads();

    int trow = tid >> 4;
    int tcol = tid & 15;
    int r0 = trow * 8, jb = tcol * 8;

    unsigned long long acc[8][4];
#pragma unroll
    for (int i = 0; i < 8; i++)
#pragma unroll
        for (int jq = 0; jq < 4; jq++) acc[i][jq] = 0ull;

#pragma unroll 4
    for (int kk = 0; kk < KCH; kk++) {
        F4U a0, a1, w0, w1;
        a0.v = *(float4*)&As[kk * AS_STRIDE + r0];
        a1.v = *(float4*)&As[kk * AS_STRIDE + r0 + 4];
        w0.v = *(float4*)&Ws[kk * WS_STRIDE + jb];
        w1.v = *(float4*)&Ws[kk * WS_STRIDE + jb + 4];
        unsigned long long wp0 = w0.u[0], wp1 = w0.u[1], wp2 = w1.u[0], wp3 = w1.u[1];
        float af[8] = {a0.f[0], a0.f[1], a0.f[2], a0.f[3],
                       a1.f[0], a1.f[1], a1.f[2], a1.f[3]};
#pragma unroll
        for (int i = 0; i < 8; i++) {
            unsigned long long ap;
            asm("mov.b64 %0, {%1, %1};" : "=l"(ap) : "f"(af[i]));
            asm("fma.rn.f32x2 %0, %1, %2, %0;" : "+l"(acc[i][0]) : "l"(ap), "l"(wp0));
            asm("fma.rn.f32x2 %0, %1, %2, %0;" : "+l"(acc[i][1]) : "l"(ap), "l"(wp1));
            asm("fma.rn.f32x2 %0, %1, %2, %0;" : "+l"(acc[i][2]) : "l"(ap), "l"(wp2));
            asm("fma.rn.f32x2 %0, %1, %2, %0;" : "+l"(acc[i][3]) : "l"(ap), "l"(wp3));
        }
    }

    if (jb < Nhead) {
        long base = (long)(blockIdx.y * 64) * Ntot + z * Nhead + j0 + jb;
#pragma unroll
        for (int i = 0; i < 8; i++) {
            F4U o0, o1;
            o0.u[0] = acc[i][0]; o0.u[1] = acc[i][1];
            o1.u[0] = acc[i][2]; o1.u[1] = acc[i][3];
            *(float4*)(P + base + (long)(r0 + i) * Ntot)     = o0.v;
            *(float4*)(P + base + (long)(r0 + i) * Ntot + 4) = o1.v;
        }
    }
}

// ---------------- layer-3 epilogue + layer 4 + dueling combine ----------------
__global__ void k_final(const float* __restrict__ vb3, const float* __restrict__ ab3,
                        const float* __restrict__ vW4, const float* __restrict__ vb4,
                        const float* __restrict__ aW4, const float* __restrict__ ab4,
                        float* __restrict__ out) {
    __shared__ float h[BGRAPH][129];
    __shared__ float res[BGRAPH][9];
    int tid = threadIdx.x;          // 576 threads
    for (int e = tid; e < BGRAPH * 128; e += 576) {
        int col = e & 127;
        float s = 0.f;
#pragma unroll
        for (int c = 0; c < 8; c++) s += g_p3[c * BGRAPH * 128 + e];
        s += (col < 64) ? vb3[col] : ab3[col - 64];
        h[e >> 7][col] = fmaxf(s, 0.f);
    }
    __syncthreads();
    {
        int b = tid / 9, j = tid % 9;
        const float* hrow = &h[b][(j == 0) ? 0 : 64];
        float s = (j == 0) ? vb4[0] : ab4[j - 1];
        if (j == 0) {
#pragma unroll 8
            for (int c = 0; c < 64; c++) s = fmaf(hrow[c], vW4[c], s);
        } else {
#pragma unroll 8
            for (int c = 0; c < 64; c++) s = fmaf(hrow[c], aW4[c * A_DIM + (j - 1)], s);
        }
        res[b][j] = s;
    }
    __syncthreads();
    if (tid < 512) {
        int b = tid >> 3, i = tid & 7;
        float m = 0.f;
#pragma unroll
        for (int q = 1; q < 9; q++) m += res[b][q];
        m *= 0.125f;
        out[tid] = res[b][0] + res[b][1 + i] - m;
    }
}

// ---------------- launch ----------------
extern "C" void kernel_launch(void* const* d_in, const int* in_sizes, int n_in,
                              void* d_out, int out_size) {
    const float* x       = (const float*)d_in[0];
    const int*   ei      = (const int*)  d_in[1];
    const int*   tls     = (const int*)  d_in[2];
    const float* W       = (const float*)d_in[3];
    const float* att_src = (const float*)d_in[4];
    const float* att_dst = (const float*)d_in[5];
    const float* b_gat   = (const float*)d_in[6];
    const float* vW1 = (const float*)d_in[7];  const float* vb1 = (const float*)d_in[8];
    const float* vW2 = (const float*)d_in[9];  const float* vb2 = (const float*)d_in[10];
    const float* vW3 = (const float*)d_in[11]; const float* vb3 = (const float*)d_in[12];
    const float* vW4 = (const float*)d_in[13]; const float* vb4 = (const float*)d_in[14];
    const float* aW1 = (const float*)d_in[15]; const float* ab1 = (const float*)d_in[16];
    const float* aW2 = (const float*)d_in[17]; const float* ab2 = (const float*)d_in[18];
    const float* aW3 = (const float*)d_in[19]; const float* ab3 = (const float*)d_in[20];
    const float* aW4 = (const float*)d_in[21]; const float* ab4 = (const float*)d_in[22];

    float* p1 = nullptr; float* p2 = nullptr; float* p3 = nullptr; float* ft = nullptr;
    cudaGetSymbolAddress((void**)&p1, g_p1);
    cudaGetSymbolAddress((void**)&p2, g_p2);
    cudaGetSymbolAddress((void**)&p3, g_p3);
    cudaGetSymbolAddress((void**)&ft, g_feats);

    k_pre<<<128 + 2050, 256>>>(x, W, att_src, att_dst, ei, tls);
    k_agg<<<NSLOTS, 128>>>(x, W, tls, b_gat);

    // L1: feats[64,1024] @ {vW1,aW1}[1024,1024] -> p1 (32 chunks, Ntot 2048)
    k_gemm<<<dim3(8, 32, 2), 128>>>(ft, 0, 1024, 0, nullptr, nullptr,
                                    vW1, aW1, p1, 1024, 2048);
    // L2: relu(sum p1 + b1)[64,1024/head] @ {vW2,aW2}[1024,256] -> p2 (32 chunks)
    k_gemm<<<dim3(2, 32, 2), 128>>>(p1, 32, 2048, 1024, vb1, ab1,
                                    vW2, aW2, p2, 256, 512);
    // L3: relu(sum p2 + b2)[64,256/head] @ {vW3,aW3}[256,64] -> p3 (8 chunks)
    k_gemm<<<dim3(1, 8, 2), 128>>>(p2, 32, 512, 256, vb2, ab2,
                                   vW3, aW3, p3, 64, 128);
    // L3 epilogue + L4 + dueling combine
    k_final<<<1, 576>>>(vb3, ab3, vW4, vb4, aW4, ab4, (float*)d_out);
}

// round 5
// speedup vs baseline: 7.9612x; 1.1667x over previous
#include <cuda_runtime.h>
#include <cstdint>
#include <math_constants.h>

#define N_NODES 32768
#define N_PER   512
#define BGRAPH  64
#define E_EDGES 524288
#define C_IN    32
#define HDIM    128
#define KTLS    8
#define A_DIM   8
#define NSLOTS  512
#define ECAP    1024
#define KCH     64

// ---------------- scratch (device globals; no allocs allowed) ----------------
__device__ float g_as[N_NODES];
__device__ float g_ad[N_NODES];
__device__ int   g_cur[NSLOTS];          // zero-init at load; k_agg re-zeros
__device__ int   g_srcs[NSLOTS * ECAP];
__device__ __align__(16) float g_feats[BGRAPH * 1024];
__device__ __align__(16) float g_h1[BGRAPH * 2048];   // RED-accumulated, pre-bias
__device__ __align__(16) float g_h2[BGRAPH * 512];
__device__ __align__(16) float g_h3[BGRAPH * 128];

__device__ __forceinline__ void red_add_v4(float* addr, float a, float b, float c, float d) {
    asm volatile("red.global.add.v4.f32 [%0], {%1,%2,%3,%4};"
                 :: "l"(addr), "f"(a), "f"(b), "f"(c), "f"(d) : "memory");
}

// ---------------- fused att + edge-filter + buffer-zero kernel ----------------
// blocks [0,128): node attention scalars; [128,2178): edge filter; [2178,2346): zero h1/h2/h3
__global__ void k_pre(const float* __restrict__ x, const float* __restrict__ W,
                      const float* __restrict__ att_src, const float* __restrict__ att_dst,
                      const int* __restrict__ ei, const int* __restrict__ tls) {
    __shared__ float ws[C_IN], wd[C_IN];
    __shared__ int tl[KTLS];
    int t = threadIdx.x;
    if (blockIdx.x < 128) {
        if (t < 64) {
            int c = t & 31;
            const float* av = (t < 32) ? att_src : att_dst;
            float s = 0.f;
#pragma unroll 8
            for (int d = 0; d < HDIM; d++) s = fmaf(W[c * HDIM + d], av[d], s);
            if (t < 32) ws[c] = s; else wd[c] = s;
        }
        __syncthreads();
        int n = blockIdx.x * 256 + t;
        const float4* xr = (const float4*)(x + n * C_IN);
        float s1 = 0.f, s2 = 0.f;
#pragma unroll
        for (int q = 0; q < 8; q++) {
            float4 v = xr[q];
            s1 = fmaf(v.x, ws[q*4+0], s1); s2 = fmaf(v.x, wd[q*4+0], s2);
            s1 = fmaf(v.y, ws[q*4+1], s1); s2 = fmaf(v.y, wd[q*4+1], s2);
            s1 = fmaf(v.z, ws[q*4+2], s1); s2 = fmaf(v.z, wd[q*4+2], s2);
            s1 = fmaf(v.w, ws[q*4+3], s1); s2 = fmaf(v.w, wd[q*4+3], s2);
        }
        g_as[n] = s1;
        g_ad[n] = s2;
    } else if (blockIdx.x < 2178) {
        if (t < KTLS) tl[t] = tls[t];
        __syncthreads();
        long i = (long)(blockIdx.x - 128) * 256 + t;     // < 524800 exactly
        if (i < E_EDGES) {
            int d = ei[E_EDGES + i];
            int loc = d & (N_PER - 1);
            int b = d >> 9;
            int s = -1;
#pragma unroll
            for (int k = 0; k < KTLS; k++) {
                if (tl[k] == loc) {
                    if (s < 0) s = ei[i];
                    int slot = b * KTLS + k;
                    int p = atomicAdd(&g_cur[slot], 1);
                    if (p < ECAP) g_srcs[slot * ECAP + p] = s;
                }
            }
        } else {                                          // self loops
            int slot = (int)(i - E_EDGES);
            int b = slot >> 3, k = slot & 7;
            int n = b * N_PER + tl[k];
            int p = atomicAdd(&g_cur[slot], 1);
            if (p < ECAP) g_srcs[slot * ECAP + p] = n;
        }
    } else {
        int i = (blockIdx.x - 2178) * 256 + t;            // < 43008 float4s
        float4 z = make_float4(0.f, 0.f, 0.f, 0.f);
        if (i < 32768)        ((float4*)g_h1)[i] = z;
        else if (i < 40960)   ((float4*)g_h2)[i - 32768] = z;
        else                  ((float4*)g_h3)[i - 40960] = z;
    }
}

// ---------------- per-target softmax + aggregation -> feats ----------------
__global__ void k_agg(const float* __restrict__ x, const float* __restrict__ W,
                      const int* __restrict__ tls, const float* __restrict__ b_gat) {
    __shared__ float Ws[C_IN * HDIM];
    __shared__ float e_s[ECAP];
    __shared__ int   s_s[ECAP];
    __shared__ float racc[4][HDIM];
    __shared__ float rden[4];
    __shared__ float red4[4];
    __shared__ float m_sh;

    int slot = blockIdx.x;
    int b = slot >> 3, k = slot & 7;
    int t = threadIdx.x;
    int w = t >> 5, l = t & 31;
    int n = b * N_PER + tls[k];
    float ad_n = g_ad[n];
    int deg = g_cur[slot];
    if (deg > ECAP) deg = ECAP;

    {
        const float4* Wg = (const float4*)W;
        float4* Wl = (float4*)Ws;
        for (int u = t; u < C_IN * HDIM / 4; u += 128) Wl[u] = Wg[u];
    }

    float lmax = -CUDART_INF_F;
    for (int j = t; j < deg; j += 128) {
        int s = g_srcs[slot * ECAP + j];
        float e = g_as[s] + ad_n;
        e = e > 0.f ? e : 0.2f * e;
        e_s[j] = e;
        s_s[j] = s;
        lmax = fmaxf(lmax, e);
    }
#pragma unroll
    for (int off = 16; off; off >>= 1)
        lmax = fmaxf(lmax, __shfl_xor_sync(0xFFFFFFFFu, lmax, off));
    if (l == 0) red4[w] = lmax;
    __syncthreads();
    if (t == 0) m_sh = fmaxf(fmaxf(red4[0], red4[1]), fmaxf(red4[2], red4[3]));
    __syncthreads();
    float m = m_sh;

    float4 acc = make_float4(0.f, 0.f, 0.f, 0.f);
    float den = 0.f;
    const float4* Ws4 = (const float4*)Ws;
    for (int j = w; j < deg; j += 4) {
        int s = s_s[j];
        float ex = __expf(e_s[j] - m);
        den += ex;
        float xv = x[s * C_IN + l];
        float4 h = make_float4(0.f, 0.f, 0.f, 0.f);
#pragma unroll
        for (int c = 0; c < C_IN; c++) {
            float xc = __shfl_sync(0xFFFFFFFFu, xv, c);
            float4 wv = Ws4[c * 32 + l];
            h.x = fmaf(xc, wv.x, h.x);
            h.y = fmaf(xc, wv.y, h.y);
            h.z = fmaf(xc, wv.z, h.z);
            h.w = fmaf(xc, wv.w, h.w);
        }
        acc.x = fmaf(ex, h.x, acc.x);
        acc.y = fmaf(ex, h.y, acc.y);
        acc.z = fmaf(ex, h.z, acc.z);
        acc.w = fmaf(ex, h.w, acc.w);
    }
    *((float4*)&racc[w][4 * l]) = acc;
    if (l == 0) rden[w] = den;
    __syncthreads();

    float tot = racc[0][t] + racc[1][t] + racc[2][t] + racc[3][t];
    float dtot = rden[0] + rden[1] + rden[2] + rden[3];
    float v = tot / (dtot + 1e-16f) + b_gat[t];
    v = v > 0.f ? v : expm1f(v);
    g_feats[b * (KTLS * HDIM) + k * HDIM + t] = v;
    if (t == 0) g_cur[slot] = 0;       // reset cursor for next graph replay
}

// ---------------- split-K SGEMM, RED accumulation into pre-zeroed output ------
// Block tile: 64 rows x 64 cols x KCH=64. 128 threads, thread tile 8x4.
// grid (Nhead/64, Kd/KCH, 2). Output O[row][z*Nhead + col], rowstride 2*Nhead.
// If fuse != 0, A element = relu(Ain + bias) (previous layer raw + bias).
#define AS_STRIDE 68
#define WS_STRIDE 68

union F4U { float4 v; unsigned long long u[2]; float f[4]; };

__global__ void __launch_bounds__(128) k_gemm(
        const float* __restrict__ Ain, int fuse, int ldin, int zstride,
        const float* __restrict__ bv_in, const float* __restrict__ ba_in,
        const float* __restrict__ Wv, const float* __restrict__ Wa,
        float* __restrict__ O, int Nhead) {
    __shared__ float As[KCH * AS_STRIDE];
    __shared__ float Ws[KCH * WS_STRIDE];

    int z  = blockIdx.z;
    const float* Wg = z ? Wa : Wv;
    int k0 = blockIdx.y * KCH;
    int j0 = blockIdx.x * 64;
    int tid = threadIdx.x;

    // stage A chunk (64 rows x KCH), transposed As[k][row]
    {
        int colbase = z * zstride + k0;
        const float* bin = z ? ba_in : bv_in;
        for (int e = tid; e < 64 * (KCH / 4); e += 128) {
            int r = e >> 4, kq = e & 15;
            float4 v = *(const float4*)(Ain + (long)r * ldin + colbase + kq * 4);
            if (fuse) {
                float4 bb = *(const float4*)(bin + k0 + kq * 4);
                v.x = fmaxf(v.x + bb.x, 0.f);
                v.y = fmaxf(v.y + bb.y, 0.f);
                v.z = fmaxf(v.z + bb.z, 0.f);
                v.w = fmaxf(v.w + bb.w, 0.f);
            }
            As[(kq * 4 + 0) * AS_STRIDE + r] = v.x;
            As[(kq * 4 + 1) * AS_STRIDE + r] = v.y;
            As[(kq * 4 + 2) * AS_STRIDE + r] = v.z;
            As[(kq * 4 + 3) * AS_STRIDE + r] = v.w;
        }
    }
    // stage W chunk (KCH rows x 64 cols)
    for (int e = tid; e < KCH * 16; e += 128) {
        int kk = e >> 4, jq = e & 15;
        float4 v = *(const float4*)(Wg + (long)(k0 + kk) * Nhead + j0 + jq * 4);
        *(float4*)&Ws[kk * WS_STRIDE + jq * 4] = v;
    }
    __syncthreads();

    int r0 = (tid >> 4) * 8;      // 8 row-groups
    int jb = (tid & 15) * 4;      // 16 col-groups of 4

    // acc[rp][j]: f32x2 pair of rows (r0+2rp, r0+2rp+1), column jb+j
    unsigned long long acc[4][4];
#pragma unroll
    for (int i = 0; i < 4; i++)
#pragma unroll
        for (int j = 0; j < 4; j++) acc[i][j] = 0ull;

#pragma unroll 4
    for (int kk = 0; kk < KCH; kk++) {
        F4U a0, a1, w;
        a0.v = *(float4*)&As[kk * AS_STRIDE + r0];       // rows r0..r0+3
        a1.v = *(float4*)&As[kk * AS_STRIDE + r0 + 4];   // rows r0+4..r0+7
        w.v  = *(float4*)&Ws[kk * WS_STRIDE + jb];
        unsigned long long ap[4] = {a0.u[0], a0.u[1], a1.u[0], a1.u[1]};
#pragma unroll
        for (int j = 0; j < 4; j++) {
            unsigned long long wd;
            asm("mov.b64 %0, {%1, %1};" : "=l"(wd) : "f"(w.f[j]));
            asm("fma.rn.f32x2 %0, %1, %2, %0;" : "+l"(acc[0][j]) : "l"(ap[0]), "l"(wd));
            asm("fma.rn.f32x2 %0, %1, %2, %0;" : "+l"(acc[1][j]) : "l"(ap[1]), "l"(wd));
            asm("fma.rn.f32x2 %0, %1, %2, %0;" : "+l"(acc[2][j]) : "l"(ap[2]), "l"(wd));
            asm("fma.rn.f32x2 %0, %1, %2, %0;" : "+l"(acc[3][j]) : "l"(ap[3]), "l"(wd));
        }
    }

    // RED-accumulate 8 rows x 4 cols into O
    int ntot = 2 * Nhead;
    float* obase = O + z * Nhead + j0 + jb;
#pragma unroll
    for (int rp = 0; rp < 4; rp++) {
        float lo[4], hi[4];
#pragma unroll
        for (int j = 0; j < 4; j++)
            asm("mov.b64 {%0, %1}, %2;" : "=f"(lo[j]), "=f"(hi[j]) : "l"(acc[rp][j]));
        red_add_v4(obase + (long)(r0 + 2 * rp)     * ntot, lo[0], lo[1], lo[2], lo[3]);
        red_add_v4(obase + (long)(r0 + 2 * rp + 1) * ntot, hi[0], hi[1], hi[2], hi[3]);
    }
}

// ---------------- layer-3 epilogue + layer 4 + dueling combine ----------------
__global__ void k_final(const float* __restrict__ vb3, const float* __restrict__ ab3,
                        const float* __restrict__ vW4, const float* __restrict__ vb4,
                        const float* __restrict__ aW4, const float* __restrict__ ab4,
                        float* __restrict__ out) {
    __shared__ float h[BGRAPH][129];
    __shared__ float res[BGRAPH][9];
    int tid = threadIdx.x;          // 576 threads
    for (int e = tid; e < BGRAPH * 128; e += 576) {
        int col = e & 127;
        float s = g_h3[e] + ((col < 64) ? vb3[col] : ab3[col - 64]);
        h[e >> 7][col] = fmaxf(s, 0.f);
    }
    __syncthreads();
    {
        int b = tid / 9, j = tid % 9;
        const float* hrow = &h[b][(j == 0) ? 0 : 64];
        float s = (j == 0) ? vb4[0] : ab4[j - 1];
        if (j == 0) {
#pragma unroll 8
            for (int c = 0; c < 64; c++) s = fmaf(hrow[c], vW4[c], s);
        } else {
#pragma unroll 8
            for (int c = 0; c < 64; c++) s = fmaf(hrow[c], aW4[c * A_DIM + (j - 1)], s);
        }
        res[b][j] = s;
    }
    __syncthreads();
    if (tid < 512) {
        int b = tid >> 3, i = tid & 7;
        float m = 0.f;
#pragma unroll
        for (int q = 1; q < 9; q++) m += res[b][q];
        m *= 0.125f;
        out[tid] = res[b][0] + res[b][1 + i] - m;
    }
}

// ---------------- launch ----------------
extern "C" void kernel_launch(void* const* d_in, const int* in_sizes, int n_in,
                              void* d_out, int out_size) {
    const float* x       = (const float*)d_in[0];
    const int*   ei      = (const int*)  d_in[1];
    const int*   tls     = (const int*)  d_in[2];
    const float* W       = (const float*)d_in[3];
    const float* att_src = (const float*)d_in[4];
    const float* att_dst = (const float*)d_in[5];
    const float* b_gat   = (const float*)d_in[6];
    const float* vW1 = (const float*)d_in[7];  const float* vb1 = (const float*)d_in[8];
    const float* vW2 = (const float*)d_in[9];  const float* vb2 = (const float*)d_in[10];
    const float* vW3 = (const float*)d_in[11]; const float* vb3 = (const float*)d_in[12];
    const float* vW4 = (const float*)d_in[13]; const float* vb4 = (const float*)d_in[14];
    const float* aW1 = (const float*)d_in[15]; const float* ab1 = (const float*)d_in[16];
    const float* aW2 = (const float*)d_in[17]; const float* ab2 = (const float*)d_in[18];
    const float* aW3 = (const float*)d_in[19]; const float* ab3 = (const float*)d_in[20];
    const float* aW4 = (const float*)d_in[21]; const float* ab4 = (const float*)d_in[22];

    float* h1 = nullptr; float* h2 = nullptr; float* h3 = nullptr; float* ft = nullptr;
    cudaGetSymbolAddress((void**)&h1, g_h1);
    cudaGetSymbolAddress((void**)&h2, g_h2);
    cudaGetSymbolAddress((void**)&h3, g_h3);
    cudaGetSymbolAddress((void**)&ft, g_feats);

    k_pre<<<2346, 256>>>(x, W, att_src, att_dst, ei, tls);
    k_agg<<<NSLOTS, 128>>>(x, W, tls, b_gat);

    // L1: feats[64,1024] @ {vW1,aW1}[1024,1024] -> RED h1 (raw)
    k_gemm<<<dim3(16, 16, 2), 128>>>(ft, 0, 1024, 0, nullptr, nullptr, vW1, aW1, h1, 1024);
    // L2: relu(h1+b1)[64,1024/head] @ {vW2,aW2}[1024,256] -> RED h2 (raw)
    k_gemm<<<dim3(4, 16, 2), 128>>>(h1, 1, 2048, 1024, vb1, ab1, vW2, aW2, h2, 256);
    // L3: relu(h2+b2)[64,256/head] @ {vW3,aW3}[256,64] -> RED h3 (raw)
    k_gemm<<<dim3(1, 4, 2), 128>>>(h2, 1, 512, 256, vb2, ab2, vW3, aW3, h3, 64);
    // L3 epilogue + L4 + dueling combine
    k_final<<<1, 576>>>(vb3, ab3, vW4, vb4, aW4, ab4, (float*)d_out);
}

// round 6
// speedup vs baseline: 10.0266x; 1.2594x over previous
#include <cuda_runtime.h>
#include <cstdint>
#include <math_constants.h>

#define N_NODES 32768
#define N_PER   512
#define BGRAPH  64
#define E_EDGES 524288
#define C_IN    32
#define HDIM    128
#define KTLS    8
#define A_DIM   8
#define NSLOTS  512
#define ECAP    1024
#define KCH     32

// ---------------- scratch (device globals; no allocs allowed) ----------------
__device__ float g_as[N_NODES];
__device__ float g_ad[N_NODES];
__device__ int   g_cur[NSLOTS];          // zero-init at load; k_agg re-zeros
__device__ int   g_srcs[NSLOTS * ECAP];
__device__ __align__(16) float g_feats[BGRAPH * 1024];
__device__ __align__(16) float g_h1[BGRAPH * 2048];   // RED-accumulated, pre-bias
__device__ __align__(16) float g_h2[BGRAPH * 512];

__device__ __forceinline__ void red_add_v4(float* addr, float a, float b, float c, float d) {
    asm volatile("red.global.add.v4.f32 [%0], {%1,%2,%3,%4};"
                 :: "l"(addr), "f"(a), "f"(b), "f"(c), "f"(d) : "memory");
}

// ---------------- fused att + edge-filter + buffer-zero kernel ----------------
// blocks [0,128): node attention scalars; [128,2178): edge filter; [2178,2338): zero h1/h2
__global__ void k_pre(const float* __restrict__ x, const float* __restrict__ W,
                      const float* __restrict__ att_src, const float* __restrict__ att_dst,
                      const int* __restrict__ ei, const int* __restrict__ tls) {
    __shared__ float ws[C_IN], wd[C_IN];
    __shared__ int tl[KTLS];
    int t = threadIdx.x;
    if (blockIdx.x < 128) {
        if (t < 64) {
            int c = t & 31;
            const float* av = (t < 32) ? att_src : att_dst;
            float s = 0.f;
#pragma unroll 8
            for (int d = 0; d < HDIM; d++) s = fmaf(W[c * HDIM + d], av[d], s);
            if (t < 32) ws[c] = s; else wd[c] = s;
        }
        __syncthreads();
        int n = blockIdx.x * 256 + t;
        const float4* xr = (const float4*)(x + n * C_IN);
        float s1 = 0.f, s2 = 0.f;
#pragma unroll
        for (int q = 0; q < 8; q++) {
            float4 v = xr[q];
            s1 = fmaf(v.x, ws[q*4+0], s1); s2 = fmaf(v.x, wd[q*4+0], s2);
            s1 = fmaf(v.y, ws[q*4+1], s1); s2 = fmaf(v.y, wd[q*4+1], s2);
            s1 = fmaf(v.z, ws[q*4+2], s1); s2 = fmaf(v.z, wd[q*4+2], s2);
            s1 = fmaf(v.w, ws[q*4+3], s1); s2 = fmaf(v.w, wd[q*4+3], s2);
        }
        g_as[n] = s1;
        g_ad[n] = s2;
    } else if (blockIdx.x < 2178) {
        if (t < KTLS) tl[t] = tls[t];
        __syncthreads();
        long i = (long)(blockIdx.x - 128) * 256 + t;     // < 524800 exactly
        if (i < E_EDGES) {
            int d = ei[E_EDGES + i];
            int loc = d & (N_PER - 1);
            int b = d >> 9;
            int s = -1;
#pragma unroll
            for (int k = 0; k < KTLS; k++) {
                if (tl[k] == loc) {
                    if (s < 0) s = ei[i];
                    int slot = b * KTLS + k;
                    int p = atomicAdd(&g_cur[slot], 1);
                    if (p < ECAP) g_srcs[slot * ECAP + p] = s;
                }
            }
        } else {                                          // self loops
            int slot = (int)(i - E_EDGES);
            int b = slot >> 3, k = slot & 7;
            int n = b * N_PER + tl[k];
            int p = atomicAdd(&g_cur[slot], 1);
            if (p < ECAP) g_srcs[slot * ECAP + p] = n;
        }
    } else {
        int i = (blockIdx.x - 2178) * 256 + t;            // < 40960 float4s
        float4 z = make_float4(0.f, 0.f, 0.f, 0.f);
        if (i < 32768)        ((float4*)g_h1)[i] = z;
        else if (i < 40960)   ((float4*)g_h2)[i - 32768] = z;
    }
}

// ---------------- per-target softmax + aggregation -> feats ----------------
__global__ void k_agg(const float* __restrict__ x, const float* __restrict__ W,
                      const int* __restrict__ tls, const float* __restrict__ b_gat) {
    __shared__ float Ws[C_IN * HDIM];
    __shared__ float e_s[ECAP];
    __shared__ int   s_s[ECAP];
    __shared__ float racc[4][HDIM];
    __shared__ float rden[4];
    __shared__ float red4[4];
    __shared__ float m_sh;

    int slot = blockIdx.x;
    int b = slot >> 3, k = slot & 7;
    int t = threadIdx.x;
    int w = t >> 5, l = t & 31;
    int n = b * N_PER + tls[k];
    float ad_n = g_ad[n];
    int deg = g_cur[slot];
    if (deg > ECAP) deg = ECAP;

    {
        const float4* Wg = (const float4*)W;
        float4* Wl = (float4*)Ws;
        for (int u = t; u < C_IN * HDIM / 4; u += 128) Wl[u] = Wg[u];
    }

    float lmax = -CUDART_INF_F;
    for (int j = t; j < deg; j += 128) {
        int s = g_srcs[slot * ECAP + j];
        float e = g_as[s] + ad_n;
        e = e > 0.f ? e : 0.2f * e;
        e_s[j] = e;
        s_s[j] = s;
        lmax = fmaxf(lmax, e);
    }
#pragma unroll
    for (int off = 16; off; off >>= 1)
        lmax = fmaxf(lmax, __shfl_xor_sync(0xFFFFFFFFu, lmax, off));
    if (l == 0) red4[w] = lmax;
    __syncthreads();
    if (t == 0) m_sh = fmaxf(fmaxf(red4[0], red4[1]), fmaxf(red4[2], red4[3]));
    __syncthreads();
    float m = m_sh;

    float4 acc = make_float4(0.f, 0.f, 0.f, 0.f);
    float den = 0.f;
    const float4* Ws4 = (const float4*)Ws;
    for (int j = w; j < deg; j += 4) {
        int s = s_s[j];
        float ex = __expf(e_s[j] - m);
        den += ex;
        float xv = x[s * C_IN + l];
        float4 h = make_float4(0.f, 0.f, 0.f, 0.f);
#pragma unroll
        for (int c = 0; c < C_IN; c++) {
            float xc = __shfl_sync(0xFFFFFFFFu, xv, c);
            float4 wv = Ws4[c * 32 + l];
            h.x = fmaf(xc, wv.x, h.x);
            h.y = fmaf(xc, wv.y, h.y);
            h.z = fmaf(xc, wv.z, h.z);
            h.w = fmaf(xc, wv.w, h.w);
        }
        acc.x = fmaf(ex, h.x, acc.x);
        acc.y = fmaf(ex, h.y, acc.y);
        acc.z = fmaf(ex, h.z, acc.z);
        acc.w = fmaf(ex, h.w, acc.w);
    }
    *((float4*)&racc[w][4 * l]) = acc;
    if (l == 0) rden[w] = den;
    __syncthreads();

    float tot = racc[0][t] + racc[1][t] + racc[2][t] + racc[3][t];
    float dtot = rden[0] + rden[1] + rden[2] + rden[3];
    float v = tot / (dtot + 1e-16f) + b_gat[t];
    v = v > 0.f ? v : expm1f(v);
    g_feats[b * (KTLS * HDIM) + k * HDIM + t] = v;
    if (t == 0) g_cur[slot] = 0;       // reset cursor for next graph replay
}

// ---------------- split-K SGEMM, RED accumulation into pre-zeroed output ------
// Block tile: 64 rows x 64 cols x KCH=32. 128 threads, thread tile 8x4 (f32x2 row pairs).
// grid (Nhead/64, Kd/KCH, 2). Output O[row][z*Nhead + col], rowstride 2*Nhead.
#define AS_STRIDE 68
#define WS_STRIDE 68

union F4U { float4 v; unsigned long long u[2]; float f[4]; };

__global__ void __launch_bounds__(128) k_gemm(
        const float* __restrict__ Ain, int fuse, int ldin, int zstride,
        const float* __restrict__ bv_in, const float* __restrict__ ba_in,
        const float* __restrict__ Wv, const float* __restrict__ Wa,
        float* __restrict__ O, int Nhead) {
    __shared__ float As[KCH * AS_STRIDE];
    __shared__ float Ws[KCH * WS_STRIDE];

    int z  = blockIdx.z;
    const float* Wg = z ? Wa : Wv;
    int k0 = blockIdx.y * KCH;
    int j0 = blockIdx.x * 64;
    int tid = threadIdx.x;

    // stage A chunk (64 rows x KCH), transposed As[k][row]
    {
        int colbase = z * zstride + k0;
        const float* bin = z ? ba_in : bv_in;
        for (int e = tid; e < 64 * (KCH / 4); e += 128) {
            int r = e >> 3, kq = e & 7;
            float4 v = *(const float4*)(Ain + (long)r * ldin + colbase + kq * 4);
            if (fuse) {
                float4 bb = *(const float4*)(bin + k0 + kq * 4);
                v.x = fmaxf(v.x + bb.x, 0.f);
                v.y = fmaxf(v.y + bb.y, 0.f);
                v.z = fmaxf(v.z + bb.z, 0.f);
                v.w = fmaxf(v.w + bb.w, 0.f);
            }
            As[(kq * 4 + 0) * AS_STRIDE + r] = v.x;
            As[(kq * 4 + 1) * AS_STRIDE + r] = v.y;
            As[(kq * 4 + 2) * AS_STRIDE + r] = v.z;
            As[(kq * 4 + 3) * AS_STRIDE + r] = v.w;
        }
    }
    // stage W chunk (KCH rows x 64 cols)
    for (int e = tid; e < KCH * 16; e += 128) {
        int kk = e >> 4, jq = e & 15;
        float4 v = *(const float4*)(Wg + (long)(k0 + kk) * Nhead + j0 + jq * 4);
        *(float4*)&Ws[kk * WS_STRIDE + jq * 4] = v;
    }
    __syncthreads();

    int r0 = (tid >> 4) * 8;      // 8 row-groups
    int jb = (tid & 15) * 4;      // 16 col-groups of 4

    unsigned long long acc[4][4];
#pragma unroll
    for (int i = 0; i < 4; i++)
#pragma unroll
        for (int j = 0; j < 4; j++) acc[i][j] = 0ull;

#pragma unroll 8
    for (int kk = 0; kk < KCH; kk++) {
        F4U a0, a1, w;
        a0.v = *(float4*)&As[kk * AS_STRIDE + r0];
        a1.v = *(float4*)&As[kk * AS_STRIDE + r0 + 4];
        w.v  = *(float4*)&Ws[kk * WS_STRIDE + jb];
        unsigned long long ap[4] = {a0.u[0], a0.u[1], a1.u[0], a1.u[1]};
#pragma unroll
        for (int j = 0; j < 4; j++) {
            unsigned long long wd;
            asm("mov.b64 %0, {%1, %1};" : "=l"(wd) : "f"(w.f[j]));
            asm("fma.rn.f32x2 %0, %1, %2, %0;" : "+l"(acc[0][j]) : "l"(ap[0]), "l"(wd));
            asm("fma.rn.f32x2 %0, %1, %2, %0;" : "+l"(acc[1][j]) : "l"(ap[1]), "l"(wd));
            asm("fma.rn.f32x2 %0, %1, %2, %0;" : "+l"(acc[2][j]) : "l"(ap[2]), "l"(wd));
            asm("fma.rn.f32x2 %0, %1, %2, %0;" : "+l"(acc[3][j]) : "l"(ap[3]), "l"(wd));
        }
    }

    int ntot = 2 * Nhead;
    float* obase = O + z * Nhead + j0 + jb;
#pragma unroll
    for (int rp = 0; rp < 4; rp++) {
        float lo[4], hi[4];
#pragma unroll
        for (int j = 0; j < 4; j++)
            asm("mov.b64 {%0, %1}, %2;" : "=f"(lo[j]), "=f"(hi[j]) : "l"(acc[rp][j]));
        red_add_v4(obase + (long)(r0 + 2 * rp)     * ntot, lo[0], lo[1], lo[2], lo[3]);
        red_add_v4(obase + (long)(r0 + 2 * rp + 1) * ntot, hi[0], hi[1], hi[2], hi[3]);
    }
}

// ---------------- per-graph tail: L2-epilogue + L3 + L4 + dueling combine -----
// 64 blocks (one per graph) x 256 threads.
__global__ void __launch_bounds__(256) k_tail(
        const float* __restrict__ vb2, const float* __restrict__ ab2,
        const float* __restrict__ vW3, const float* __restrict__ vb3,
        const float* __restrict__ aW3, const float* __restrict__ ab3,
        const float* __restrict__ vW4, const float* __restrict__ vb4,
        const float* __restrict__ aW4, const float* __restrict__ ab4,
        float* __restrict__ out) {
    __shared__ float h2s[512];
    __shared__ float part[128][2];
    __shared__ float h3s[128];
    __shared__ float res[9];
    int b = blockIdx.x;
    int t = threadIdx.x;

    // L2 epilogue: relu(h2_raw + bias)
    for (int e = t; e < 512; e += 256) {
        float s = g_h2[b * 512 + e] + ((e < 256) ? vb2[e] : ab2[e - 256]);
        h2s[e] = fmaxf(s, 0.f);
    }
    __syncthreads();

    // L3: 128 outputs, K=256 split into two halves across thread pairs
    {
        int o = t & 127;          // output index
        int half = t >> 7;        // K half
        int head = o >> 6, j = o & 63;
        const float* W3 = head ? aW3 : vW3;
        const float* hh = h2s + head * 256 + half * 128;
        const float* wp = W3 + (half * 128) * 64 + j;
        float s = 0.f;
#pragma unroll 8
        for (int kq = 0; kq < 128; kq++) s = fmaf(hh[kq], wp[kq * 64], s);
        part[o][half] = s;
    }
    __syncthreads();
    if (t < 128) {
        int head = t >> 6, j = t & 63;
        float s = part[t][0] + part[t][1] + (head ? ab3[j] : vb3[j]);
        h3s[t] = fmaxf(s, 0.f);
    }
    __syncthreads();

    // L4: 9 dots of length 64
    if (t < 9) {
        const float* hrow = &h3s[(t == 0) ? 0 : 64];
        float s = (t == 0) ? vb4[0] : ab4[t - 1];
        if (t == 0) {
#pragma unroll 8
            for (int c = 0; c < 64; c++) s = fmaf(hrow[c], vW4[c], s);
        } else {
#pragma unroll 8
            for (int c = 0; c < 64; c++) s = fmaf(hrow[c], aW4[c * A_DIM + (t - 1)], s);
        }
        res[t] = s;
    }
    __syncthreads();
    if (t < 8) {
        float m = 0.f;
#pragma unroll
        for (int q = 1; q < 9; q++) m += res[q];
        m *= 0.125f;
        out[b * A_DIM + t] = res[0] + res[1 + t] - m;
    }
}

// ---------------- launch ----------------
extern "C" void kernel_launch(void* const* d_in, const int* in_sizes, int n_in,
                              void* d_out, int out_size) {
    const float* x       = (const float*)d_in[0];
    const int*   ei      = (const int*)  d_in[1];
    const int*   tls     = (const int*)  d_in[2];
    const float* W       = (const float*)d_in[3];
    const float* att_src = (const float*)d_in[4];
    const float* att_dst = (const float*)d_in[5];
    const float* b_gat   = (const float*)d_in[6];
    const float* vW1 = (const float*)d_in[7];  const float* vb1 = (const float*)d_in[8];
    const float* vW2 = (const float*)d_in[9];  const float* vb2 = (const float*)d_in[10];
    const float* vW3 = (const float*)d_in[11]; const float* vb3 = (const float*)d_in[12];
    const float* vW4 = (const float*)d_in[13]; const float* vb4 = (const float*)d_in[14];
    const float* aW1 = (const float*)d_in[15]; const float* ab1 = (const float*)d_in[16];
    const float* aW2 = (const float*)d_in[17]; const float* ab2 = (const float*)d_in[18];
    const float* aW3 = (const float*)d_in[19]; const float* ab3 = (const float*)d_in[20];
    const float* aW4 = (const float*)d_in[21]; const float* ab4 = (const float*)d_in[22];

    float* h1 = nullptr; float* h2 = nullptr; float* ft = nullptr;
    cudaGetSymbolAddress((void**)&h1, g_h1);
    cudaGetSymbolAddress((void**)&h2, g_h2);
    cudaGetSymbolAddress((void**)&ft, g_feats);

    k_pre<<<2338, 256>>>(x, W, att_src, att_dst, ei, tls);
    k_agg<<<NSLOTS, 128>>>(x, W, tls, b_gat);

    // L1: feats[64,1024] @ {vW1,aW1}[1024,1024] -> RED h1 (raw)
    k_gemm<<<dim3(16, 32, 2), 128>>>(ft, 0, 1024, 0, nullptr, nullptr, vW1, aW1, h1, 1024);
    // L2: relu(h1+b1)[64,1024/head] @ {vW2,aW2}[1024,256] -> RED h2 (raw)
    k_gemm<<<dim3(4, 32, 2), 128>>>(h1, 1, 2048, 1024, vb1, ab1, vW2, aW2, h2, 256);
    // L2-epilogue + L3 + L4 + combine, per graph
    k_tail<<<BGRAPH, 256>>>(vb2, ab2, vW3, vb3, aW3, ab3, vW4, vb4, aW4, ab4, (float*)d_out);
}